// round 15
// baseline (speedup 1.0000x reference)
#include <cuda_runtime.h>
#include <mma.h>
#include <math.h>

using namespace nvcuda;

#define Bz 16
#define Cc 512
#define Hh 28
#define Ww 28
#define Nn 784
#define NH 8
#define HD 64
#define Rr 32
#define Mrows (Bz*Nn)   // 12544

// ---------------- scratch ----------------
__device__ float g_chs[Bz*Cc];
__device__ float g_pmax[Bz*8*Nn];
__device__ float g_psum[Bz*8*Nn];
__device__ float g_sg[Bz*Nn];
__device__ float g_q  [Mrows*Cc];
__device__ float g_k  [Mrows*Cc];
__device__ float g_v  [Mrows*Cc];
__device__ float g_att[Mrows*Cc];
__device__ float g_o  [Mrows*Cc];
__device__ float g_pool[Bz*Cc];
__device__ float g_part[Bz*16*Cc];

// ---------------- K1: fused channel pools + gate MLP ----------------
__global__ __launch_bounds__(512) void k_poolmlp(const float* __restrict__ x,
                          const float* __restrict__ w1, const float* __restrict__ b1,
                          const float* __restrict__ w2, const float* __restrict__ b2) {
    int b = blockIdx.x;
    int tid = threadIdx.x, lane = tid & 31, w = tid >> 5;
    __shared__ float sa[Cc], sx[Cc], ha[Rr], hm[Rr];
    for (int c = w; c < Cc; c += 16) {
        const float4* p = (const float4*)(x + ((long)(b*Cc + c))*Nn);
        float s = 0.f, m = -1e30f;
        for (int i = lane; i < Nn/4; i += 32) {
            float4 v = p[i];
            s += v.x+v.y+v.z+v.w;
            m = fmaxf(m, fmaxf(fmaxf(v.x,v.y), fmaxf(v.z,v.w)));
        }
        #pragma unroll
        for (int o = 16; o > 0; o >>= 1) {
            s += __shfl_xor_sync(0xffffffffu, s, o);
            m = fmaxf(m, __shfl_xor_sync(0xffffffffu, m, o));
        }
        if (lane == 0) { sa[c] = s / (float)Nn; sx[c] = m; }
    }
    __syncthreads();
    if (tid < Rr) {
        int r = tid;
        float s1 = b1[r], s2 = b1[r];
        for (int i = 0; i < Cc; i++) { float wv = w1[r*Cc+i]; s1 += wv*sa[i]; s2 += wv*sx[i]; }
        ha[r] = fmaxf(s1, 0.f); hm[r] = fmaxf(s2, 0.f);
    }
    __syncthreads();
    {
        int c = tid;
        float s = 2.f * b2[c];
        #pragma unroll
        for (int r = 0; r < Rr; r++) s += w2[c*Rr+r] * (ha[r] + hm[r]);
        g_chs[b*Cc+c] = 1.f / (1.f + expf(-s));
    }
}

// ---------------- K2a: per-pixel channel max/mean over 64-channel chunk ----------------
__global__ void k_gate1(const float* __restrict__ x) {
    int b = blockIdx.x, pc = blockIdx.y, cch = blockIdx.z;   // (Bz,4,8)
    int p = pc*196 + threadIdx.x;
    __shared__ float chs[64];
    if (threadIdx.x < 64) chs[threadIdx.x] = g_chs[b*Cc + cch*64 + threadIdx.x];
    __syncthreads();
    float mx = -1e30f, s = 0.f;
    #pragma unroll 8
    for (int c0 = 0; c0 < 64; c0++) {
        int c = cch*64 + c0;
        float v = x[((long)(b*Cc+c))*Nn + p] * chs[c0];
        mx = fmaxf(mx, v); s += v;
    }
    g_pmax[(b*8+cch)*Nn + p] = mx;
    g_psum[(b*8+cch)*Nn + p] = s;
}

// ---------------- K2b: reduce chunks, 7x7 conv + BN + sigmoid ----------------
__global__ void k_gate2(const float* __restrict__ sp_w,
                        const float* __restrict__ gam, const float* __restrict__ bet,
                        const float* __restrict__ mu,  const float* __restrict__ var) {
    int b = blockIdx.x, p = threadIdx.x;
    __shared__ float cmax[Nn], cmean[Nn], wsm[98];
    float mx = -1e30f, s = 0.f;
    #pragma unroll
    for (int ch = 0; ch < 8; ch++) {
        mx = fmaxf(mx, g_pmax[(b*8+ch)*Nn + p]);
        s += g_psum[(b*8+ch)*Nn + p];
    }
    cmax[p] = mx; cmean[p] = s * (1.f/(float)Cc);
    if (p < 98) wsm[p] = sp_w[p];
    __syncthreads();
    int py = p / Ww, px = p % Ww;
    float acc = 0.f;
    #pragma unroll
    for (int ky = 0; ky < 7; ky++) {
        int yy = py + ky - 3; if (yy < 0 || yy >= Hh) continue;
        #pragma unroll
        for (int kx = 0; kx < 7; kx++) {
            int xx = px + kx - 3; if (xx < 0 || xx >= Ww) continue;
            int q = yy*Ww + xx;
            acc += wsm[ky*7+kx] * cmax[q] + wsm[49+ky*7+kx] * cmean[q];
        }
    }
    float sv = (acc - mu[0]) * rsqrtf(var[0] + 1e-5f) * gam[0] + bet[0];
    g_sg[b*Nn+p] = 1.f / (1.f + expf(-sv));
}

// ---------------- K3: tf32 wmma GEMM 128x128 (R13-proven) ----------------
#define GS 36
template<int MODE>
__global__ __launch_bounds__(256) void k_gemm4(const float* __restrict__ X,
                        const float* __restrict__ W0, const float* __restrict__ W1,
                        const float* __restrict__ W2, const float* __restrict__ bb0,
                        const float* __restrict__ bb1, const float* __restrict__ bb2) {
    __shared__ float As[128*GS];
    __shared__ float Bs[128*GS];
    int m0 = blockIdx.y*128, n0 = blockIdx.x*128;
    const float* W; const float* bias; float* Out;
    if (MODE == 0) {
        int z = blockIdx.z;
        W    = (z==0) ? W0 : (z==1) ? W1 : W2;
        bias = (z==0) ? bb0 : (z==1) ? bb1 : bb2;
        Out  = (z==0) ? g_q : (z==1) ? g_k : g_v;
    } else { W = W0; bias = bb0; Out = g_o; }
    int tid = threadIdx.x, wid = tid >> 5;
    int warp_m = wid & 1, warp_n = wid >> 1;

    wmma::fragment<wmma::accumulator,16,16,8,float> acc[4][2];
    #pragma unroll
    for (int i = 0; i < 4; i++)
        #pragma unroll
        for (int j = 0; j < 2; j++) wmma::fill_fragment(acc[i][j], 0.f);

    for (int k0 = 0; k0 < Cc+32; k0 += 32) {
        if (k0 < Cc) {
            if (MODE == 0) {
                #pragma unroll
                for (int t = 0; t < 16; t++) {
                    int idx = tid + t*256;
                    int mm = idx & 127, kk = idx >> 7;
                    int gm = m0 + mm;
                    int bb = gm / Nn, nn = gm - bb*Nn;
                    float v = X[((long)(bb*Cc + k0+kk))*Nn + nn]
                            * g_chs[bb*Cc + k0+kk] * g_sg[gm];
                    As[mm*GS+kk] = wmma::__float_to_tf32(v);
                }
            } else {
                #pragma unroll
                for (int t = 0; t < 16; t++) {
                    int idx = tid + t*256;
                    int kk = idx & 31, mm = idx >> 5;
                    As[mm*GS+kk] = wmma::__float_to_tf32(g_att[(long)(m0+mm)*Cc + k0+kk]);
                }
            }
            #pragma unroll
            for (int t = 0; t < 16; t++) {
                int idx = tid + t*256;
                int kk = idx & 31, nn = idx >> 5;
                Bs[nn*GS+kk] = wmma::__float_to_tf32(W[(long)(n0+nn)*Cc + k0+kk]);
            }
        } else {
            #pragma unroll
            for (int t = 0; t < 16; t++) {
                int idx = tid + t*256;
                int mm = idx & 127, kk = idx >> 7;
                As[mm*GS+kk] = (kk == 0) ? wmma::__float_to_tf32(1.f) : 0.f;
                Bs[mm*GS+kk] = (kk == 0) ? wmma::__float_to_tf32(bias[n0+mm]) : 0.f;
            }
        }
        __syncthreads();
        #pragma unroll
        for (int ks = 0; ks < 4; ks++) {
            wmma::fragment<wmma::matrix_a,16,16,8,wmma::precision::tf32,wmma::row_major> af[4];
            wmma::fragment<wmma::matrix_b,16,16,8,wmma::precision::tf32,wmma::col_major> bf[2];
            #pragma unroll
            for (int i = 0; i < 4; i++)
                wmma::load_matrix_sync(af[i], &As[(warp_m*64 + i*16)*GS + ks*8], GS);
            #pragma unroll
            for (int j = 0; j < 2; j++)
                wmma::load_matrix_sync(bf[j], &Bs[(warp_n*32 + j*16)*GS + ks*8], GS);
            #pragma unroll
            for (int i = 0; i < 4; i++)
                #pragma unroll
                for (int j = 0; j < 2; j++) wmma::mma_sync(acc[i][j], af[i], bf[j], acc[i][j]);
        }
        __syncthreads();
    }
    #pragma unroll
    for (int i = 0; i < 4; i++)
        #pragma unroll
        for (int j = 0; j < 2; j++)
            wmma::store_matrix_sync(Out + (long)(m0 + warp_m*64 + i*16)*Cc + n0 + warp_n*32 + j*16,
                                    acc[i][j], Cc, wmma::mem_row_major);
}

// ---------------- K4: flash attention, tf32 wmma ----------------
#define TMq 64
#define TNK 128
#define FST 68    // Q/K/V stride (mod 32 = 4, float4-aligned)
#define PST 132   // P stride    (mod 32 = 4)
__global__ __launch_bounds__(256) void k_flashw() {
    extern __shared__ float smf[];
    float* Qs = smf;                  // [64][68] tf32
    float* Ks = Qs + TMq*FST;         // [128][68] tf32 (K, then V)
    float* Ps = Ks + TNK*FST;         // [64][132] scores/P(tf32)/O-tile
    float* Os = Ps + TMq*PST;         // [64][68] fp32 running O
    __shared__ float m_s[TMq], l_s[TMq], alpha_s[TMq];
    __shared__ float redmx[4][TMq], redsm[4][TMq];
    int n0 = blockIdx.x*TMq, h = blockIdx.y, b = blockIdx.z;
    int tid = threadIdx.x, wid = tid >> 5;
    int warp_m = wid & 1, warp_n = wid >> 1;   // QK: 2x4, warp tile 32x32
    int pwm = wid & 3, pwn = wid >> 2;         // PV: 4x2, warp tile 16x32
    int r = tid & 63, part = tid >> 6;

    // stage Q (tf32, clamped rows)
    for (int idx = tid; idx < TMq*16; idx += 256) {
        int rr = idx >> 4, dq = (idx & 15)*4;
        int n = n0 + rr; if (n > Nn-1) n = Nn-1;
        float4 v = *(const float4*)&g_q[((long)(b*Nn + n))*Cc + h*HD + dq];
        float4 t = {wmma::__float_to_tf32(v.x), wmma::__float_to_tf32(v.y),
                    wmma::__float_to_tf32(v.z), wmma::__float_to_tf32(v.w)};
        *(float4*)&Qs[rr*FST+dq] = t;
    }
    for (int e = tid; e < TMq*HD; e += 256) {
        int rr = e >> 6, d = e & 63;
        Os[rr*FST+d] = 0.f;
    }
    if (tid < TMq) { m_s[tid] = -1e30f; l_s[tid] = 0.f; }

    for (int kt = 0; kt < Nn; kt += TNK) {
        __syncthreads();
        // stage K (tf32)
        for (int idx = tid; idx < TNK*16; idx += 256) {
            int rr = idx >> 4, dq = (idx & 15)*4;
            int m = kt + rr; if (m > Nn-1) m = Nn-1;
            float4 v = *(const float4*)&g_k[((long)(b*Nn + m))*Cc + h*HD + dq];
            float4 t = {wmma::__float_to_tf32(v.x), wmma::__float_to_tf32(v.y),
                        wmma::__float_to_tf32(v.z), wmma::__float_to_tf32(v.w)};
            *(float4*)&Ks[rr*FST+dq] = t;
        }
        __syncthreads();
        // S = Q K^T * scale ; warp tile 32x32 = 2x2 frags
        {
            wmma::fragment<wmma::accumulator,16,16,8,float> sacc[2][2];
            #pragma unroll
            for (int i = 0; i < 2; i++)
                #pragma unroll
                for (int j = 0; j < 2; j++) wmma::fill_fragment(sacc[i][j], 0.f);
            #pragma unroll
            for (int ks = 0; ks < 8; ks++) {
                wmma::fragment<wmma::matrix_a,16,16,8,wmma::precision::tf32,wmma::row_major> af[2];
                wmma::fragment<wmma::matrix_b,16,16,8,wmma::precision::tf32,wmma::col_major> bf[2];
                #pragma unroll
                for (int i = 0; i < 2; i++)
                    wmma::load_matrix_sync(af[i], &Qs[(warp_m*32 + i*16)*FST + ks*8], FST);
                #pragma unroll
                for (int j = 0; j < 2; j++)
                    wmma::load_matrix_sync(bf[j], &Ks[(warp_n*32 + j*16)*FST + ks*8], FST);
                #pragma unroll
                for (int i = 0; i < 2; i++)
                    #pragma unroll
                    for (int j = 0; j < 2; j++) wmma::mma_sync(sacc[i][j], af[i], bf[j], sacc[i][j]);
            }
            #pragma unroll
            for (int i = 0; i < 2; i++)
                #pragma unroll
                for (int j = 0; j < 2; j++) {
                    #pragma unroll
                    for (int e = 0; e < sacc[i][j].num_elements; e++) sacc[i][j].x[e] *= 0.125f;
                    wmma::store_matrix_sync(&Ps[(warp_m*32 + i*16)*PST + warp_n*32 + j*16],
                                            sacc[i][j], PST, wmma::mem_row_major);
                }
        }
        __syncthreads();
        // stage V (tf32, overwrites Ks) + scalar softmax on Ps
        for (int idx = tid; idx < TNK*16; idx += 256) {
            int rr = idx >> 4, dq = (idx & 15)*4;
            int m = kt + rr; if (m > Nn-1) m = Nn-1;
            float4 v = *(const float4*)&g_v[((long)(b*Nn + m))*Cc + h*HD + dq];
            float4 t = {wmma::__float_to_tf32(v.x), wmma::__float_to_tf32(v.y),
                        wmma::__float_to_tf32(v.z), wmma::__float_to_tf32(v.w)};
            *(float4*)&Ks[rr*FST+dq] = t;
        }
        int vc = (Nn - kt < TNK) ? (Nn - kt) : TNK;
        float lm = -1e30f;
        for (int c = part*32; c < part*32+32; c++)
            if (c < vc) lm = fmaxf(lm, Ps[r*PST+c]);
        redmx[part][r] = lm;
        __syncthreads();
        if (tid < TMq) {
            float tm = fmaxf(fmaxf(redmx[0][tid],redmx[1][tid]), fmaxf(redmx[2][tid],redmx[3][tid]));
            float nm = fmaxf(m_s[tid], tm);
            alpha_s[tid] = __expf(m_s[tid] - nm);
            m_s[tid] = nm;
        }
        __syncthreads();
        float nm = m_s[r], ls = 0.f;
        for (int c = part*32; c < part*32+32; c++) {
            if (c < vc) {
                float e = __expf(Ps[r*PST+c] - nm);
                Ps[r*PST+c] = wmma::__float_to_tf32(e);
                ls += e;
            } else Ps[r*PST+c] = 0.f;
        }
        redsm[part][r] = ls;
        __syncthreads();
        if (tid < TMq) l_s[tid] = l_s[tid]*alpha_s[tid]
                                + redsm[0][tid]+redsm[1][tid]+redsm[2][tid]+redsm[3][tid];
        // O_tile = P V ; warp tile 16x32 = 1x2 frags
        wmma::fragment<wmma::accumulator,16,16,8,float> oacc[2];
        #pragma unroll
        for (int j = 0; j < 2; j++) wmma::fill_fragment(oacc[j], 0.f);
        #pragma unroll
        for (int ks = 0; ks < 16; ks++) {
            wmma::fragment<wmma::matrix_a,16,16,8,wmma::precision::tf32,wmma::row_major> af;
            wmma::load_matrix_sync(af, &Ps[(pwm*16)*PST + ks*8], PST);
            #pragma unroll
            for (int j = 0; j < 2; j++) {
                wmma::fragment<wmma::matrix_b,16,16,8,wmma::precision::tf32,wmma::row_major> bf;
                wmma::load_matrix_sync(bf, &Ks[(ks*8)*FST + pwn*32 + j*16], FST);
                wmma::mma_sync(oacc[j], af, bf, oacc[j]);
            }
        }
        __syncthreads();   // all P reads done before Ps becomes the O tile
        #pragma unroll
        for (int j = 0; j < 2; j++)
            wmma::store_matrix_sync(&Ps[(pwm*16)*PST + pwn*32 + j*16], oacc[j], PST, wmma::mem_row_major);
        __syncthreads();
        // merge: Os = Os*alpha + O_tile
        for (int e = tid; e < TMq*HD; e += 256) {
            int rr = e >> 6, d = e & 63;
            Os[rr*FST+d] = Os[rr*FST+d]*alpha_s[rr] + Ps[rr*PST+d];
        }
    }
    __syncthreads();
    for (int e = tid; e < TMq*HD; e += 256) {
        int rr = e >> 6, d = e & 63;
        int row = n0 + rr;
        if (row < Nn)
            g_att[((long)(b*Nn + row))*Cc + h*HD + d] = Os[rr*FST+d] / l_s[rr];
    }
}

// ---------------- K5a: pooled sum of x*chs*sg over pixels ----------------
__global__ void k_pool_y2(const float* __restrict__ x) {
    int c = blockIdx.x, b = blockIdx.y;
    const float* p = x + (long)(b*Cc+c)*Nn;
    const float* sg = g_sg + b*Nn;
    float s = 0.f;
    for (int i = threadIdx.x; i < Nn; i += 256) s += p[i]*sg[i];
    __shared__ float ss[256];
    ss[threadIdx.x] = s; __syncthreads();
    for (int o = 128; o > 0; o >>= 1) { if (threadIdx.x < o) ss[threadIdx.x] += ss[threadIdx.x+o]; __syncthreads(); }
    if (threadIdx.x == 0) g_pool[b*Cc+c] = ss[0] * g_chs[b*Cc+c];
}

// ---------------- K5b: partial pooled sums of O ----------------
__global__ void k_pool_o2() {
    int b = blockIdx.x, chunk = blockIdx.y;   // (Bz,16)
    int p0 = chunk*49;
    int c = threadIdx.x;
    float s0 = 0.f, s1 = 0.f;
    for (int p = p0; p < p0+49; p++) {
        const float* row = g_o + (long)(b*Nn+p)*Cc;
        s0 += row[c]; s1 += row[c+256];
    }
    g_part[(long)(b*16+chunk)*Cc + c]       = s0;
    g_part[(long)(b*16+chunk)*Cc + c + 256] = s1;
}

// ---------------- K6: classifier ----------------
__global__ void k_head(const float* __restrict__ lng, const float* __restrict__ lnb,
                       const float* __restrict__ f1w, const float* __restrict__ f1b,
                       const float* __restrict__ f2w, const float* __restrict__ f2b,
                       float* __restrict__ out) {
    int b = blockIdx.x, t = threadIdx.x;
    __shared__ float pv[512], ln[512], hsm[512], red[512];
    float acc = g_pool[b*Cc+t];
    #pragma unroll
    for (int j = 0; j < 16; j++) acc += g_part[(long)(b*16+j)*Cc + t];
    pv[t] = acc * (1.f/(float)Nn);
    __syncthreads();
    red[t] = pv[t]; __syncthreads();
    for (int o = 256; o > 0; o >>= 1) { if (t < o) red[t] += red[t+o]; __syncthreads(); }
    float mu = red[0] * (1.f/512.f); __syncthreads();
    float dv = pv[t] - mu;
    red[t] = dv*dv; __syncthreads();
    for (int o = 256; o > 0; o >>= 1) { if (t < o) red[t] += red[t+o]; __syncthreads(); }
    float var = red[0] * (1.f/512.f);
    float rs = rsqrtf(var + 1e-5f);
    ln[t] = dv * rs * lng[t] + lnb[t];
    __syncthreads();
    float s = f1b[t];
    for (int i = 0; i < 512; i++) s += f1w[t*512+i] * ln[i];
    hsm[t] = fmaxf(s, 0.f);
    __syncthreads();
    red[t] = f2w[t] * hsm[t]; __syncthreads();
    for (int o = 256; o > 0; o >>= 1) { if (t < o) red[t] += red[t+o]; __syncthreads(); }
    if (t == 0) out[b] = red[0] + f2b[0];
}

// ---------------- launch ----------------
extern "C" void kernel_launch(void* const* d_in, const int* in_sizes, int n_in,
                              void* d_out, int out_size) {
    const float* x       = (const float*)d_in[0];
    const float* mlp_w1  = (const float*)d_in[1];
    const float* mlp_b1  = (const float*)d_in[2];
    const float* mlp_w2  = (const float*)d_in[3];
    const float* mlp_b2  = (const float*)d_in[4];
    const float* sp_w    = (const float*)d_in[5];
    const float* sp_gam  = (const float*)d_in[6];
    const float* sp_bet  = (const float*)d_in[7];
    const float* sp_mean = (const float*)d_in[8];
    const float* sp_var  = (const float*)d_in[9];
    const float* wq      = (const float*)d_in[10];
    const float* bq      = (const float*)d_in[11];
    const float* wk      = (const float*)d_in[12];
    const float* bk      = (const float*)d_in[13];
    const float* wv      = (const float*)d_in[14];
    const float* bv      = (const float*)d_in[15];
    const float* wo      = (const float*)d_in[16];
    const float* bo      = (const float*)d_in[17];
    const float* ln_g    = (const float*)d_in[18];
    const float* ln_b    = (const float*)d_in[19];
    const float* fc1_w   = (const float*)d_in[20];
    const float* fc1_b   = (const float*)d_in[21];
    const float* fc2_w   = (const float*)d_in[22];
    const float* fc2_b   = (const float*)d_in[23];
    float* out = (float*)d_out;

    static int smem_set = 0;
    int flash_smem = (TMq*FST + TNK*FST + TMq*PST + TMq*FST) * 4;   // 103,424 B
    if (!smem_set) {
        cudaFuncSetAttribute(k_flashw, cudaFuncAttributeMaxDynamicSharedMemorySize, flash_smem);
        smem_set = 1;
    }

    k_poolmlp<<<Bz, 512>>>(x, mlp_w1, mlp_b1, mlp_w2, mlp_b2);
    k_gate1  <<<dim3(Bz, 4, 8), 196>>>(x);
    k_gate2  <<<Bz, Nn>>>(sp_w, sp_gam, sp_bet, sp_mean, sp_var);

    k_gemm4<0><<<dim3(4, 98, 3), 256>>>(x, wq, wk, wv, bq, bk, bv);

    k_flashw<<<dim3((Nn + TMq - 1)/TMq, NH, Bz), 256, flash_smem>>>();

    k_gemm4<3><<<dim3(4, 98, 1), 256>>>(0, wo, 0, 0, bo, 0, 0);

    k_pool_y2<<<dim3(Cc, Bz), 256>>>(x);
    k_pool_o2<<<dim3(Bz, 16), 256>>>();
    k_head  <<<Bz, 512>>>(ln_g, ln_b, fc1_w, fc1_b, fc2_w, fc2_b, out);
}

// round 16
// speedup vs baseline: 1.1842x; 1.1842x over previous
#include <cuda_runtime.h>
#include <mma.h>
#include <math.h>

using namespace nvcuda;

#define Bz 16
#define Cc 512
#define Hh 28
#define Ww 28
#define Nn 784
#define NH 8
#define HD 64
#define Rr 32
#define Mrows (Bz*Nn)   // 12544

// ---------------- scratch ----------------
__device__ float g_chs[Bz*Cc];
__device__ float g_pmax[Bz*8*Nn];
__device__ float g_psum[Bz*8*Nn];
__device__ float g_sg[Bz*Nn];
__device__ float g_xt [Mrows*Cc];   // gated x, row-major [m, c]
__device__ float g_q  [Mrows*Cc];
__device__ float g_k  [Mrows*Cc];
__device__ float g_v  [Mrows*Cc];
__device__ float g_att[Mrows*Cc];
__device__ float g_o  [Mrows*Cc];
__device__ float g_pool[Bz*Cc];
__device__ float g_part[Bz*16*Cc];

// ---------------- K1: fused channel pools + gate MLP ----------------
__global__ __launch_bounds__(512) void k_poolmlp(const float* __restrict__ x,
                          const float* __restrict__ w1, const float* __restrict__ b1,
                          const float* __restrict__ w2, const float* __restrict__ b2) {
    int b = blockIdx.x;
    int tid = threadIdx.x, lane = tid & 31, w = tid >> 5;
    __shared__ float sa[Cc], sx[Cc], ha[Rr], hm[Rr];
    for (int c = w; c < Cc; c += 16) {
        const float4* p = (const float4*)(x + ((long)(b*Cc + c))*Nn);
        float s = 0.f, m = -1e30f;
        for (int i = lane; i < Nn/4; i += 32) {
            float4 v = p[i];
            s += v.x+v.y+v.z+v.w;
            m = fmaxf(m, fmaxf(fmaxf(v.x,v.y), fmaxf(v.z,v.w)));
        }
        #pragma unroll
        for (int o = 16; o > 0; o >>= 1) {
            s += __shfl_xor_sync(0xffffffffu, s, o);
            m = fmaxf(m, __shfl_xor_sync(0xffffffffu, m, o));
        }
        if (lane == 0) { sa[c] = s / (float)Nn; sx[c] = m; }
    }
    __syncthreads();
    if (tid < Rr) {
        int r = tid;
        float s1 = b1[r], s2 = b1[r];
        for (int i = 0; i < Cc; i++) { float wv = w1[r*Cc+i]; s1 += wv*sa[i]; s2 += wv*sx[i]; }
        ha[r] = fmaxf(s1, 0.f); hm[r] = fmaxf(s2, 0.f);
    }
    __syncthreads();
    {
        int c = tid;
        float s = 2.f * b2[c];
        #pragma unroll
        for (int r = 0; r < Rr; r++) s += w2[c*Rr+r] * (ha[r] + hm[r]);
        g_chs[b*Cc+c] = 1.f / (1.f + expf(-s));
    }
}

// ---------------- K2a: per-pixel channel max/mean over 64-channel chunk ----------------
__global__ void k_gate1(const float* __restrict__ x) {
    int b = blockIdx.x, pc = blockIdx.y, cch = blockIdx.z;   // (Bz,4,8)
    int p = pc*196 + threadIdx.x;
    __shared__ float chs[64];
    if (threadIdx.x < 64) chs[threadIdx.x] = g_chs[b*Cc + cch*64 + threadIdx.x];
    __syncthreads();
    float mx = -1e30f, s = 0.f;
    #pragma unroll 8
    for (int c0 = 0; c0 < 64; c0++) {
        int c = cch*64 + c0;
        float v = x[((long)(b*Cc+c))*Nn + p] * chs[c0];
        mx = fmaxf(mx, v); s += v;
    }
    g_pmax[(b*8+cch)*Nn + p] = mx;
    g_psum[(b*8+cch)*Nn + p] = s;
}

// ---------------- K2b: reduce chunks, 7x7 conv + BN + sigmoid ----------------
__global__ void k_gate2(const float* __restrict__ sp_w,
                        const float* __restrict__ gam, const float* __restrict__ bet,
                        const float* __restrict__ mu,  const float* __restrict__ var) {
    int b = blockIdx.x, p = threadIdx.x;
    __shared__ float cmax[Nn], cmean[Nn], wsm[98];
    float mx = -1e30f, s = 0.f;
    #pragma unroll
    for (int ch = 0; ch < 8; ch++) {
        mx = fmaxf(mx, g_pmax[(b*8+ch)*Nn + p]);
        s += g_psum[(b*8+ch)*Nn + p];
    }
    cmax[p] = mx; cmean[p] = s * (1.f/(float)Cc);
    if (p < 98) wsm[p] = sp_w[p];
    __syncthreads();
    int py = p / Ww, px = p % Ww;
    float acc = 0.f;
    #pragma unroll
    for (int ky = 0; ky < 7; ky++) {
        int yy = py + ky - 3; if (yy < 0 || yy >= Hh) continue;
        #pragma unroll
        for (int kx = 0; kx < 7; kx++) {
            int xx = px + kx - 3; if (xx < 0 || xx >= Ww) continue;
            int q = yy*Ww + xx;
            acc += wsm[ky*7+kx] * cmax[q] + wsm[49+ky*7+kx] * cmean[q];
        }
    }
    float sv = (acc - mu[0]) * rsqrtf(var[0] + 1e-5f) * gam[0] + bet[0];
    g_sg[b*Nn+p] = 1.f / (1.f + expf(-sv));
}

// ---------------- K2c: build gated transposed X (g_xt[m,c] = x*chs*sg) ----------------
#define XTS 521   // smem row stride (odd -> conflict-free transpose)
__global__ __launch_bounds__(256) void k_xform(const float* __restrict__ x) {
    __shared__ float sm[16*XTS];
    __shared__ float chs[Cc], sg16[16];
    int b = blockIdx.x, p0 = blockIdx.y*16;
    int tid = threadIdx.x;
    for (int i = tid; i < Cc; i += 256) chs[i] = g_chs[b*Cc+i];
    if (tid < 16) sg16[tid] = g_sg[b*Nn + p0 + tid];
    __syncthreads();
    #pragma unroll
    for (int t = 0; t < 32; t++) {
        int idx = tid + t*256;             // 8192 = 512c x 16p
        int c = idx >> 4, p = idx & 15;
        float v = x[((long)(b*Cc+c))*Nn + p0 + p] * chs[c] * sg16[p];
        sm[p*XTS + c] = v;
    }
    __syncthreads();
    #pragma unroll
    for (int t = 0; t < 32; t++) {
        int idx = tid + t*256;
        int p = idx >> 9, c = idx & 511;
        g_xt[((long)(b*Nn + p0 + p))*Cc + c] = sm[p*XTS + c];
    }
}

// ---------------- K3: tf32 wmma GEMM 128x128, double-buffered ----------------
// MODE 0: A = g_xt, z selects Q/K/V.  MODE 3: A = g_att -> g_o
#define GS 36
template<int MODE>
__global__ __launch_bounds__(256) void k_gemm5(
                        const float* __restrict__ W0, const float* __restrict__ W1,
                        const float* __restrict__ W2, const float* __restrict__ bb0,
                        const float* __restrict__ bb1, const float* __restrict__ bb2) {
    extern __shared__ float smg[];
    float* As = smg;                 // [2][128*GS]
    float* Bs = smg + 2*128*GS;      // [2][128*GS]
    int m0 = blockIdx.y*128, n0 = blockIdx.x*128;
    const float* Asrc; const float* W; const float* bias; float* Out;
    if (MODE == 0) {
        int z = blockIdx.z;
        Asrc = g_xt;
        W    = (z==0) ? W0 : (z==1) ? W1 : W2;
        bias = (z==0) ? bb0 : (z==1) ? bb1 : bb2;
        Out  = (z==0) ? g_q : (z==1) ? g_k : g_v;
    } else { Asrc = g_att; W = W0; bias = bb0; Out = g_o; }
    int tid = threadIdx.x, wid = tid >> 5;
    int warp_m = wid & 1, warp_n = wid >> 1;   // 2x4 warps, warp tile 64x32

    wmma::fragment<wmma::accumulator,16,16,8,float> acc[4][2];
    #pragma unroll
    for (int i = 0; i < 4; i++)
        #pragma unroll
        for (int j = 0; j < 2; j++) wmma::fill_fragment(acc[i][j], 0.f);

    float4 ra[4], rb[4];
    int mm_[4], k4_[4];
    #pragma unroll
    for (int t = 0; t < 4; t++) {
        int idx4 = tid + t*256;
        mm_[t] = idx4 >> 3;
        k4_[t] = (idx4 & 7)*4;
    }

    // prefetch slice 0
    #pragma unroll
    for (int t = 0; t < 4; t++) {
        ra[t] = *(const float4*)&Asrc[(long)(m0+mm_[t])*Cc + k4_[t]];
        rb[t] = *(const float4*)&W[(long)(n0+mm_[t])*Cc + k4_[t]];
    }
    // store slice 0 -> buf 0
    #pragma unroll
    for (int t = 0; t < 4; t++) {
        float4 a = ra[t], bvv = rb[t];
        float4 at = {wmma::__float_to_tf32(a.x), wmma::__float_to_tf32(a.y),
                     wmma::__float_to_tf32(a.z), wmma::__float_to_tf32(a.w)};
        float4 bt = {wmma::__float_to_tf32(bvv.x), wmma::__float_to_tf32(bvv.y),
                     wmma::__float_to_tf32(bvv.z), wmma::__float_to_tf32(bvv.w)};
        *(float4*)&As[mm_[t]*GS + k4_[t]] = at;
        *(float4*)&Bs[mm_[t]*GS + k4_[t]] = bt;
    }
    __syncthreads();

    for (int kt = 0; kt <= 16; kt++) {       // 16 data slices + 1 bias slice
        int cur = kt & 1;
        // prefetch slice kt+1
        if (kt < 15) {
            int k0 = (kt+1)*32;
            #pragma unroll
            for (int t = 0; t < 4; t++) {
                ra[t] = *(const float4*)&Asrc[(long)(m0+mm_[t])*Cc + k0 + k4_[t]];
                rb[t] = *(const float4*)&W[(long)(n0+mm_[t])*Cc + k0 + k4_[t]];
            }
        } else if (kt == 15) {
            // bias slice: A[:,0]=1, B[n,0]=bias[n]
            #pragma unroll
            for (int t = 0; t < 4; t++) {
                float av = (k4_[t] == 0) ? 1.f : 0.f;
                float bv2 = (k4_[t] == 0) ? bias[n0+mm_[t]] : 0.f;
                ra[t] = {av, 0.f, 0.f, 0.f};
                rb[t] = {bv2, 0.f, 0.f, 0.f};
            }
        }
        // compute on buf cur
        float* Ac = As + cur*128*GS;
        float* Bc = Bs + cur*128*GS;
        #pragma unroll
        for (int ks = 0; ks < 4; ks++) {
            wmma::fragment<wmma::matrix_a,16,16,8,wmma::precision::tf32,wmma::row_major> af[4];
            wmma::fragment<wmma::matrix_b,16,16,8,wmma::precision::tf32,wmma::col_major> bf[2];
            #pragma unroll
            for (int i = 0; i < 4; i++)
                wmma::load_matrix_sync(af[i], &Ac[(warp_m*64 + i*16)*GS + ks*8], GS);
            #pragma unroll
            for (int j = 0; j < 2; j++)
                wmma::load_matrix_sync(bf[j], &Bc[(warp_n*32 + j*16)*GS + ks*8], GS);
            #pragma unroll
            for (int i = 0; i < 4; i++)
                #pragma unroll
                for (int j = 0; j < 2; j++) wmma::mma_sync(acc[i][j], af[i], bf[j], acc[i][j]);
        }
        __syncthreads();
        if (kt < 16) {
            float* An = As + (cur^1)*128*GS;
            float* Bn = Bs + (cur^1)*128*GS;
            #pragma unroll
            for (int t = 0; t < 4; t++) {
                float4 a = ra[t], bvv = rb[t];
                float4 at = {wmma::__float_to_tf32(a.x), wmma::__float_to_tf32(a.y),
                             wmma::__float_to_tf32(a.z), wmma::__float_to_tf32(a.w)};
                float4 bt = {wmma::__float_to_tf32(bvv.x), wmma::__float_to_tf32(bvv.y),
                             wmma::__float_to_tf32(bvv.z), wmma::__float_to_tf32(bvv.w)};
                *(float4*)&An[mm_[t]*GS + k4_[t]] = at;
                *(float4*)&Bn[mm_[t]*GS + k4_[t]] = bt;
            }
            __syncthreads();
        }
    }
    #pragma unroll
    for (int i = 0; i < 4; i++)
        #pragma unroll
        for (int j = 0; j < 2; j++)
            wmma::store_matrix_sync(Out + (long)(m0 + warp_m*64 + i*16)*Cc + n0 + warp_n*32 + j*16,
                                    acc[i][j], Cc, wmma::mem_row_major);
}

// ---------------- K4: flash attention (R13-proven SIMT: scalar QK, float4 AV) ----------------
#define TMq 64
#define TNK 128
#define QPAD 65
#define VPAD 68
#define PPAD 132
__global__ __launch_bounds__(256) void k_flash() {
    extern __shared__ float smf[];
    float* Qs = smf;                                // [64][65]
    float* Ks = smf + TMq*QPAD;                     // [128][68] region (K stride 65, V stride 68)
    float* Ps = smf + TMq*QPAD + TNK*VPAD;          // [64][132]
    int n0 = blockIdx.x*TMq, h = blockIdx.y, b = blockIdx.z;
    int tid = threadIdx.x;
    int tx = tid & 15, ty = tid >> 4;
    for (int idx = tid; idx < TMq*16; idx += 256) {
        int r = idx >> 4, dq = (idx & 15)*4;
        int n = n0 + r; if (n > Nn-1) n = Nn-1;
        float4 v = *(const float4*)&g_q[((long)(b*Nn + n))*Cc + h*HD + dq];
        Qs[r*QPAD+dq] = v.x; Qs[r*QPAD+dq+1] = v.y; Qs[r*QPAD+dq+2] = v.z; Qs[r*QPAD+dq+3] = v.w;
    }
    float m_pr[4], l_pr[4], Oa[4][4];
    #pragma unroll
    for (int i = 0; i < 4; i++) {
        m_pr[i] = -1e30f; l_pr[i] = 0.f;
        #pragma unroll
        for (int j = 0; j < 4; j++) Oa[i][j] = 0.f;
    }
    for (int kt = 0; kt < Nn; kt += TNK) {
        __syncthreads();
        for (int idx = tid; idx < TNK*16; idx += 256) {
            int r = idx >> 4, dq = (idx & 15)*4;
            int m = kt + r; if (m > Nn-1) m = Nn-1;
            float4 v = *(const float4*)&g_k[((long)(b*Nn + m))*Cc + h*HD + dq];
            Ks[r*QPAD+dq] = v.x; Ks[r*QPAD+dq+1] = v.y; Ks[r*QPAD+dq+2] = v.z; Ks[r*QPAD+dq+3] = v.w;
        }
        __syncthreads();
        float S[4][8];
        #pragma unroll
        for (int i = 0; i < 4; i++)
            #pragma unroll
            for (int j = 0; j < 8; j++) S[i][j] = 0.f;
        #pragma unroll 4
        for (int d = 0; d < HD; d++) {
            float a[4], bv[8];
            #pragma unroll
            for (int i = 0; i < 4; i++) a[i] = Qs[(ty*4+i)*QPAD + d];
            #pragma unroll
            for (int j = 0; j < 8; j++) bv[j] = Ks[(tx + j*16)*QPAD + d];
            #pragma unroll
            for (int i = 0; i < 4; i++)
                #pragma unroll
                for (int j = 0; j < 8; j++) S[i][j] += a[i]*bv[j];
        }
        #pragma unroll
        for (int i = 0; i < 4; i++)
            #pragma unroll
            for (int j = 0; j < 8; j++) {
                int col = kt + tx + j*16;
                S[i][j] = (col < Nn) ? S[i][j]*0.125f : -1e30f;
            }
        #pragma unroll
        for (int i = 0; i < 4; i++) {
            float rm = S[i][0];
            #pragma unroll
            for (int j = 1; j < 8; j++) rm = fmaxf(rm, S[i][j]);
            #pragma unroll
            for (int o = 1; o < 16; o <<= 1) rm = fmaxf(rm, __shfl_xor_sync(0xffffffffu, rm, o));
            float nm = fmaxf(m_pr[i], rm);
            float alpha = __expf(m_pr[i] - nm);
            float rs = 0.f;
            #pragma unroll
            for (int j = 0; j < 8; j++) { float e = __expf(S[i][j] - nm); S[i][j] = e; rs += e; }
            #pragma unroll
            for (int o = 1; o < 16; o <<= 1) rs += __shfl_xor_sync(0xffffffffu, rs, o);
            l_pr[i] = l_pr[i]*alpha + rs;
            m_pr[i] = nm;
            #pragma unroll
            for (int j = 0; j < 4; j++) Oa[i][j] *= alpha;
            #pragma unroll
            for (int j = 0; j < 8; j++) Ps[(ty*4+i)*PPAD + tx + j*16] = S[i][j];
        }
        __syncthreads();
        for (int idx = tid; idx < TNK*16; idx += 256) {
            int r = idx >> 4, dq = (idx & 15)*4;
            int m = kt + r; if (m > Nn-1) m = Nn-1;
            float4 v = *(const float4*)&g_v[((long)(b*Nn + m))*Cc + h*HD + dq];
            Ks[r*VPAD+dq] = v.x; Ks[r*VPAD+dq+1] = v.y; Ks[r*VPAD+dq+2] = v.z; Ks[r*VPAD+dq+3] = v.w;
        }
        __syncthreads();
        int mmax = (Nn - kt < TNK) ? (Nn - kt) : TNK;
        for (int m2 = 0; m2 < mmax; m2++) {
            float4 v = *(float4*)&Ks[m2*VPAD + tx*4];
            #pragma unroll
            for (int i = 0; i < 4; i++) {
                float p = Ps[(ty*4+i)*PPAD + m2];
                Oa[i][0] += p*v.x; Oa[i][1] += p*v.y; Oa[i][2] += p*v.z; Oa[i][3] += p*v.w;
            }
        }
    }
    #pragma unroll
    for (int i = 0; i < 4; i++) {
        int row = n0 + ty*4 + i;
        if (row < Nn) {
            float inv = 1.f / l_pr[i];
            float4 o = {Oa[i][0]*inv, Oa[i][1]*inv, Oa[i][2]*inv, Oa[i][3]*inv};
            *(float4*)&g_att[((long)(b*Nn + row))*Cc + h*HD + tx*4] = o;
        }
    }
}

// ---------------- K5a: pooled sum of gated x over pixels (reads g_xt rows) ----------------
__global__ void k_pool_y3() {
    int b = blockIdx.x, chunk = blockIdx.y;   // (Bz,16)
    int p0 = chunk*49;
    int c = threadIdx.x;     // 256 threads, 2 channels each
    float s0 = 0.f, s1 = 0.f;
    for (int p = p0; p < p0+49; p++) {
        const float* row = g_xt + (long)(b*Nn+p)*Cc;
        s0 += row[c]; s1 += row[c+256];
    }
    g_pool[(long)(b)*Cc + c]         = s0;    // overwritten below with += via g_part trick
    g_pool[(long)(b)*Cc + c + 256]   = s1;    // NOTE: raced across chunks -> use g_part instead
}

// ---------------- K5b: partial pooled sums (xt + o share the pattern) ----------------
template<int SRC>
__global__ void k_pool_p() {
    int b = blockIdx.x, chunk = blockIdx.y;   // (Bz,16)
    const float* base = (SRC == 0) ? g_xt : g_o;
    int p0 = chunk*49;
    int c = threadIdx.x;
    float s0 = 0.f, s1 = 0.f;
    for (int p = p0; p < p0+49; p++) {
        const float* row = base + (long)(b*Nn+p)*Cc;
        s0 += row[c]; s1 += row[c+256];
    }
    float* dst = (SRC == 0) ? g_pool : g_part;   // g_pool reused as [Bz*16*Cc]? no — see below
    // store into g_part layout: SRC0 -> first 16 chunks region of g_part? keep separate arrays:
    if (SRC == 0) {
        g_pool[((long)(b*16+chunk))*Cc + c]       = s0;   // g_pool repurposed [Bz*16*Cc]? too small.
        g_pool[((long)(b*16+chunk))*Cc + c + 256] = s1;
    } else {
        g_part[((long)(b*16+chunk))*Cc + c]       = s0;
        g_part[((long)(b*16+chunk))*Cc + c + 256] = s1;
    }
}

// g_pool is Bz*Cc — too small for 16 chunks; add a dedicated buffer:
__device__ float g_partx[Bz*16*Cc];

__global__ void k_pool_px() {
    int b = blockIdx.x, chunk = blockIdx.y;   // (Bz,16)
    int p0 = chunk*49;
    int c = threadIdx.x;
    float s0 = 0.f, s1 = 0.f;
    for (int p = p0; p < p0+49; p++) {
        const float* row = g_xt + (long)(b*Nn+p)*Cc;
        s0 += row[c]; s1 += row[c+256];
    }
    g_partx[((long)(b*16+chunk))*Cc + c]       = s0;
    g_partx[((long)(b*16+chunk))*Cc + c + 256] = s1;
}

__global__ void k_pool_o2() {
    int b = blockIdx.x, chunk = blockIdx.y;   // (Bz,16)
    int p0 = chunk*49;
    int c = threadIdx.x;
    float s0 = 0.f, s1 = 0.f;
    for (int p = p0; p < p0+49; p++) {
        const float* row = g_o + (long)(b*Nn+p)*Cc;
        s0 += row[c]; s1 += row[c+256];
    }
    g_part[((long)(b*16+chunk))*Cc + c]       = s0;
    g_part[((long)(b*16+chunk))*Cc + c + 256] = s1;
}

// ---------------- K6: classifier ----------------
__global__ void k_head(const float* __restrict__ lng, const float* __restrict__ lnb,
                       const float* __restrict__ f1w, const float* __restrict__ f1b,
                       const float* __restrict__ f2w, const float* __restrict__ f2b,
                       float* __restrict__ out) {
    int b = blockIdx.x, t = threadIdx.x;
    __shared__ float pv[512], ln[512], hsm[512], red[512];
    float acc = 0.f;
    #pragma unroll
    for (int j = 0; j < 16; j++) {
        acc += g_partx[((long)(b*16+j))*Cc + t];
        acc += g_part [((long)(b*16+j))*Cc + t];
    }
    pv[t] = acc * (1.f/(float)Nn);
    __syncthreads();
    red[t] = pv[t]; __syncthreads();
    for (int o = 256; o > 0; o >>= 1) { if (t < o) red[t] += red[t+o]; __syncthreads(); }
    float mu = red[0] * (1.f/512.f); __syncthreads();
    float dv = pv[t] - mu;
    red[t] = dv*dv; __syncthreads();
    for (int o = 256; o > 0; o >>= 1) { if (t < o) red[t] += red[t+o]; __syncthreads(); }
    float var = red[0] * (1.f/512.f);
    float rs = rsqrtf(var + 1e-5f);
    ln[t] = dv * rs * lng[t] + lnb[t];
    __syncthreads();
    float s = f1b[t];
    for (int i = 0; i < 512; i++) s += f1w[t*512+i] * ln[i];
    hsm[t] = fmaxf(s, 0.f);
    __syncthreads();
    red[t] = f2w[t] * hsm[t]; __syncthreads();
    for (int o = 256; o > 0; o >>= 1) { if (t < o) red[t] += red[t+o]; __syncthreads(); }
    if (t == 0) out[b] = red[0] + f2b[0];
}

// ---------------- launch ----------------
extern "C" void kernel_launch(void* const* d_in, const int* in_sizes, int n_in,
                              void* d_out, int out_size) {
    const float* x       = (const float*)d_in[0];
    const float* mlp_w1  = (const float*)d_in[1];
    const float* mlp_b1  = (const float*)d_in[2];
    const float* mlp_w2  = (const float*)d_in[3];
    const float* mlp_b2  = (const float*)d_in[4];
    const float* sp_w    = (const float*)d_in[5];
    const float* sp_gam  = (const float*)d_in[6];
    const float* sp_bet  = (const float*)d_in[7];
    const float* sp_mean = (const float*)d_in[8];
    const float* sp_var  = (const float*)d_in[9];
    const float* wq      = (const float*)d_in[10];
    const float* bq      = (const float*)d_in[11];
    const float* wk      = (const float*)d_in[12];
    const float* bk      = (const float*)d_in[13];
    const float* wv      = (const float*)d_in[14];
    const float* bv      = (const float*)d_in[15];
    const float* wo      = (const float*)d_in[16];
    const float* bo      = (const float*)d_in[17];
    const float* ln_g    = (const float*)d_in[18];
    const float* ln_b    = (const float*)d_in[19];
    const float* fc1_w   = (const float*)d_in[20];
    const float* fc1_b   = (const float*)d_in[21];
    const float* fc2_w   = (const float*)d_in[22];
    const float* fc2_b   = (const float*)d_in[23];
    float* out = (float*)d_out;

    static int smem_set = 0;
    int flash_smem = (TMq*QPAD + TNK*VPAD + TMq*PPAD) * 4;   // 85,248 B
    int gemm_smem  = 4*128*GS*4;                              // 73,728 B
    if (!smem_set) {
        cudaFuncSetAttribute(k_flash, cudaFuncAttributeMaxDynamicSharedMemorySize, flash_smem);
        cudaFuncSetAttribute(k_gemm5<0>, cudaFuncAttributeMaxDynamicSharedMemorySize, gemm_smem);
        cudaFuncSetAttribute(k_gemm5<3>, cudaFuncAttributeMaxDynamicSharedMemorySize, gemm_smem);
        smem_set = 1;
    }

    k_poolmlp<<<Bz, 512>>>(x, mlp_w1, mlp_b1, mlp_w2, mlp_b2);
    k_gate1  <<<dim3(Bz, 4, 8), 196>>>(x);
    k_gate2  <<<Bz, Nn>>>(sp_w, sp_gam, sp_bet, sp_mean, sp_var);
    k_xform  <<<dim3(Bz, 49), 256>>>(x);

    k_gemm5<0><<<dim3(4, 98, 3), 256, gemm_smem>>>(wq, wk, wv, bq, bk, bv);

    k_flash<<<dim3((Nn + TMq - 1)/TMq, NH, Bz), 256, flash_smem>>>();

    k_gemm5<3><<<dim3(4, 98, 1), 256, gemm_smem>>>(wo, 0, 0, bo, 0, 0);

    k_pool_px<<<dim3(Bz, 16), 256>>>();
    k_pool_o2<<<dim3(Bz, 16), 256>>>();
    k_head  <<<Bz, 512>>>(ln_g, ln_b, fc1_w, fc1_b, fc2_w, fc2_b, out);
}